// round 8
// baseline (speedup 1.0000x reference)
#include <cuda_runtime.h>
#include <math.h>

#define QD 256    // queries
#define II 2048   // gallery images
#define DD 256    // feature dim

#define BQ 32
#define BI 128
#define KC 16
#define NG 4           // k-groups per block
#define KPG 64         // k per group
#define NTS 4          // tiles per group (KPG / KC)
#define QP 18          // u64 pitch for q-coeff rows (144B, 16B-aligned)

#define SGSZ   (KC * BI * 4)            // 8192 B
#define CARR   (BQ * QP * 8)            // 4608 B per coeff array
#define GRP_SZ (SGSZ + 3 * CARR)        // 22016 B
#define SMEM_SZ (NG * GRP_SZ)           // 88064 B (dynamic, opt-in)

typedef unsigned long long u64;

// ---- scratch (__device__ globals; no allocation allowed) ----
__device__ float d_C [QD * DD];   // fqn*A   natural [Q][D]
__device__ float d_A2[QD * DD];   // A^2     natural [Q][D]
__device__ float d_AB[QD * DD];   // 2*A*B   natural [Q][D]
__device__ float d_GT[DD * II];   // normalized gallery, transposed [D][I]
__device__ float d_c0[QD];
__device__ float d_b0;

// ---------------- packed f32x2 helpers ----------------
__device__ __forceinline__ u64 pack2(float lo, float hi) {
    u64 r;
    asm("mov.b64 %0, {%1, %2};" : "=l"(r) : "f"(lo), "f"(hi));
    return r;
}
__device__ __forceinline__ void unpack2(u64 v, float& lo, float& hi) {
    asm("mov.b64 {%0, %1}, %2;" : "=f"(lo), "=f"(hi) : "l"(v));
}
#define FMA2(acc, a, b) \
    asm("fma.rn.f32x2 %0, %1, %2, %0;" : "+l"(acc) : "l"(a), "l"(b))
#define FMA2R(d, a, b, c) \
    asm("fma.rn.f32x2 %0, %1, %2, %3;" : "=l"(d) : "l"(a), "l"(b), "l"(c))
#define ADD2(acc, v) \
    asm("add.rn.f32x2 %0, %0, %1;" : "+l"(acc) : "l"(v))
#define GBAR(id) \
    asm volatile("bar.sync %0, 256;" :: "r"(id) : "memory")

__device__ __forceinline__ float warpSum(float v) {
    #pragma unroll
    for (int o = 16; o; o >>= 1) v += __shfl_xor_sync(0xffffffffu, v, o);
    return v;
}

// ---------------- fused prep kernel: 64 blocks x 256 threads ----------------
__global__ __launch_bounds__(256) void prep_kernel(
        const float* __restrict__ qf,
        const float* __restrict__ qi,
        const float* __restrict__ gal,
        const float* __restrict__ gamma,
        const float* __restrict__ beta,
        const float* __restrict__ mean,
        const float* __restrict__ var) {
    const int bx  = blockIdx.x;
    const int tid = threadIdx.x;

    if (bx < 32) {
        // ---- gallery part: normalize + transpose rows i0..i0+63 ----
        __shared__ float sInv[64];
        __shared__ float sT[32][65];
        const int i0 = bx * 64;
        const int w = tid >> 5, lane = tid & 31;

        #pragma unroll
        for (int r = 0; r < 8; r++) {
            int il = w * 8 + r;
            const float4* row = (const float4*)&gal[(i0 + il) * DD];
            float4 a = row[lane];
            float4 b = row[lane + 32];
            float ss = a.x*a.x + a.y*a.y + a.z*a.z + a.w*a.w
                     + b.x*b.x + b.y*b.y + b.z*b.z + b.w*b.w;
            ss = warpSum(ss);
            if (lane == 0) sInv[il] = 1.f / fmaxf(sqrtf(ss), 1e-12f);
        }
        __syncthreads();

        for (int dc = 0; dc < DD; dc += 32) {
            #pragma unroll
            for (int it = 0; it < 2; it++) {
                int p  = tid + it * 256;
                int il = p >> 3;
                int kv = p & 7;
                float inv = sInv[il];
                float4 v = *(const float4*)&gal[(i0 + il) * DD + dc + 4 * kv];
                sT[4*kv + 0][il] = v.x * inv;
                sT[4*kv + 1][il] = v.y * inv;
                sT[4*kv + 2][il] = v.z * inv;
                sT[4*kv + 3][il] = v.w * inv;
            }
            __syncthreads();
            #pragma unroll
            for (int half = 0; half < 2; half++) {
                int dl = (tid >> 4) + 16 * half;
                int iv = tid & 15;
                float4 o;
                o.x = sT[dl][4*iv + 0];
                o.y = sT[dl][4*iv + 1];
                o.z = sT[dl][4*iv + 2];
                o.w = sT[dl][4*iv + 3];
                *(float4*)&d_GT[(dc + dl) * II + i0 + 4 * iv] = o;
            }
            __syncthreads();
        }
    } else {
        // ---- query part: warp per query ----
        const int q    = (bx - 32) * 8 + (tid >> 5);
        const int lane = tid & 31;

        float x[8], y[8], istd[8], B[8];
        float xs = 0.f, ys = 0.f;
        #pragma unroll
        for (int j = 0; j < 8; j++) {
            int d = lane + 32 * j;
            x[j] = qf[q * DD + d];
            y[j] = qi[q * DD + d];
            istd[j] = gamma[d] * rsqrtf(var[d] + 1e-5f);
            B[j] = beta[d] - mean[d] * istd[j];
            xs += x[j] * x[j];
            ys += y[j] * y[j];
        }
        xs = warpSum(xs);
        ys = warpSum(ys);
        float xin = 1.f / fmaxf(sqrtf(xs), 1e-12f);
        float yin = 1.f / fmaxf(sqrtf(ys), 1e-12f);

        float A[8], fq[8];
        float fs = 0.f;
        #pragma unroll
        for (int j = 0; j < 8; j++) {
            float xn = x[j] * xin;
            float gate = 1.f / (1.f + __expf(-xn * 5.0f));  // sigmoid(xn/0.2)
            A[j] = gate * istd[j];
            float yn = y[j] * yin;
            fq[j] = yn * A[j] + B[j];
            fs += fq[j] * fq[j];
        }
        fs = warpSum(fs);
        float fin = 1.f / fmaxf(sqrtf(fs), 1e-12f);

        float c0 = 0.f;
        #pragma unroll
        for (int j = 0; j < 8; j++) {
            int d = lane + 32 * j;
            float fqn = fq[j] * fin;
            d_C [q * DD + d] = fqn * A[j];
            d_A2[q * DD + d] = A[j] * A[j];
            d_AB[q * DD + d] = 2.f * A[j] * B[j];
            c0 += fqn * B[j];
        }
        c0 = warpSum(c0);
        if (lane == 0) d_c0[q] = c0;

        if (q == 0) {
            float b0 = 0.f;
            #pragma unroll
            for (int j = 0; j < 8; j++) b0 += B[j] * B[j];
            b0 = warpSum(b0);
            if (lane == 0) d_b0 = b0;
        }
    }
}

// ---------------- main scoring kernel ----------------
// grid (16, 8) = 128 blocks; 1024 threads = 32 warps = 4 k-groups x 8 warps.
// Group g: k in [64g, 64g+64), private smem, private named barrier (g+1).
// Within a group: warp wg owns q rows q0+4wg..+3; lane spans 4 i (BI=128).
// End: 2-round smem reduction into group 0, which runs the epilogue.
extern __shared__ __align__(16) char dyn_smem[];

__global__ __launch_bounds__(1024, 1) void score_kernel(float* __restrict__ out) {
    const int tid  = threadIdx.x;
    const int warp = tid >> 5;
    const int lane = tid & 31;
    const int gsel = warp >> 3;   // 0..3 k-group
    const int wg   = warp & 7;    // warp within group
    const int gt   = tid & 255;   // thread within group
    const int i0 = blockIdx.x * BI;
    const int q0 = blockIdx.y * BQ;

    char* gb = dyn_smem + gsel * GRP_SZ;
    float (*sG)[BI] = (float (*)[BI])(gb);
    u64   (*sC)[QP]  = (u64 (*)[QP])(gb + SGSZ);
    u64   (*sA2)[QP] = (u64 (*)[QP])(gb + SGSZ + CARR);
    u64   (*sAB)[QP] = (u64 (*)[QP])(gb + SGSZ + 2 * CARR);

    u64 s1[4][2], s2[4][2];
    #pragma unroll
    for (int u = 0; u < 4; u++) {
        s1[u][0] = 0ull; s1[u][1] = 0ull;
        s2[u][0] = 0ull; s2[u][1] = 0ull;
    }

    // loader mappings (within group)
    const int gkc = gt >> 4;   // 0..15
    const int giv = gt & 15;   // 0..15
    const int lq  = gt >> 2;   // (gt<128) 0..31
    const int lkv = gt & 3;    // 0..3

    for (int t = 0; t < NTS; t++) {
        // ---- load tile t (LDG -> STS, no persistent prefetch regs) ----
        {
            const int k0 = gsel * KPG + t * KC;
            const float* grow = &d_GT[(k0 + gkc) * II + i0];
            float4 ga = *(const float4*)&grow[4 * giv];
            float4 gbv = *(const float4*)&grow[64 + 4 * giv];
            *(float4*)&sG[gkc][4 * giv]      = ga;
            *(float4*)&sG[gkc][64 + 4 * giv] = gbv;
            if (gt < 128) {
                float4 pc = *(const float4*)&d_C [(q0 + lq) * DD + k0 + 4 * lkv];
                float4 pa = *(const float4*)&d_A2[(q0 + lq) * DD + k0 + 4 * lkv];
                float4 pb = *(const float4*)&d_AB[(q0 + lq) * DD + k0 + 4 * lkv];
                u64* c = &sC [lq][4 * lkv];
                u64* a = &sA2[lq][4 * lkv];
                u64* b = &sAB[lq][4 * lkv];
                c[0] = pack2(pc.x, pc.x); c[1] = pack2(pc.y, pc.y);
                c[2] = pack2(pc.z, pc.z); c[3] = pack2(pc.w, pc.w);
                a[0] = pack2(pa.x, pa.x); a[1] = pack2(pa.y, pa.y);
                a[2] = pack2(pa.z, pa.z); a[3] = pack2(pa.w, pa.w);
                b[0] = pack2(pb.x, pb.x); b[1] = pack2(pb.y, pb.y);
                b[2] = pack2(pb.z, pb.z); b[3] = pack2(pb.w, pb.w);
            }
        }
        GBAR(gsel + 1);

        // ---- compute tile t ----
        const u64* pC  = &sC [wg * 4][0];
        const u64* pA2 = &sA2[wg * 4][0];
        const u64* pAB = &sAB[wg * 4][0];

        #pragma unroll
        for (int kc = 0; kc < KC; kc += 2) {
            ulonglong2 g0 = *(const ulonglong2*)&sG[kc    ][4 * lane];
            ulonglong2 g1 = *(const ulonglong2*)&sG[kc + 1][4 * lane];
            #pragma unroll
            for (int u = 0; u < 4; u++) {
                ulonglong2 cp = *(const ulonglong2*)(pC  + u * QP + kc);
                ulonglong2 ap = *(const ulonglong2*)(pA2 + u * QP + kc);
                ulonglong2 bp = *(const ulonglong2*)(pAB + u * QP + kc);
                u64 t00, t01, t10, t11;
                FMA2(s1[u][0], cp.x, g0.x);
                FMA2(s1[u][1], cp.x, g0.y);
                FMA2R(t00, ap.x, g0.x, bp.x);
                FMA2R(t01, ap.x, g0.y, bp.x);
                FMA2(s2[u][0], t00, g0.x);
                FMA2(s2[u][1], t01, g0.y);
                FMA2(s1[u][0], cp.y, g1.x);
                FMA2(s1[u][1], cp.y, g1.y);
                FMA2R(t10, ap.y, g1.x, bp.y);
                FMA2R(t11, ap.y, g1.y, bp.y);
                FMA2(s2[u][0], t10, g1.x);
                FMA2(s2[u][1], t11, g1.y);
            }
        }
        GBAR(gsel + 1);   // tile fully consumed; safe to overwrite next iter
    }

    // ---- cross-group reduction: groups 1-3 -> group 0, two rounds ----
    ulonglong2* red = (ulonglong2*)dyn_smem;  // 768 thr * 4 * 16B = 48 KB

    __syncthreads();                     // S0: all mainloops done
    if (gsel) {
        int base = ((gsel - 1) * 256 + gt) * 4;
        #pragma unroll
        for (int u = 0; u < 4; u++) {
            ulonglong2 v; v.x = s1[u][0]; v.y = s1[u][1];
            red[base + u] = v;
        }
    }
    __syncthreads();                     // S1
    if (!gsel) {
        #pragma unroll
        for (int g = 0; g < 3; g++) {
            int base = (g * 256 + gt) * 4;
            #pragma unroll
            for (int u = 0; u < 4; u++) {
                ulonglong2 v = red[base + u];
                ADD2(s1[u][0], v.x); ADD2(s1[u][1], v.y);
            }
        }
    }
    __syncthreads();                     // S2
    if (gsel) {
        int base = ((gsel - 1) * 256 + gt) * 4;
        #pragma unroll
        for (int u = 0; u < 4; u++) {
            ulonglong2 v; v.x = s2[u][0]; v.y = s2[u][1];
            red[base + u] = v;
        }
    }
    __syncthreads();                     // S3
    if (!gsel) {
        #pragma unroll
        for (int g = 0; g < 3; g++) {
            int base = (g * 256 + gt) * 4;
            #pragma unroll
            for (int u = 0; u < 4; u++) {
                ulonglong2 v = red[base + u];
                ADD2(s2[u][0], v.x); ADD2(s2[u][1], v.y);
            }
        }

        // epilogue: score = sigmoid((s1+c0) / max(sqrt(s2+b0), 1e-12))
        const float b0 = d_b0;
        #pragma unroll
        for (int u = 0; u < 4; u++) {
            int q = q0 + wg * 4 + u;
            float c0 = d_c0[q];
            float a[4], b[4];
            unpack2(s1[u][0], a[0], a[1]);
            unpack2(s1[u][1], a[2], a[3]);
            unpack2(s2[u][0], b[0], b[1]);
            unpack2(s2[u][1], b[2], b[3]);
            float4 r;
            float* rp = &r.x;
            #pragma unroll
            for (int v = 0; v < 4; v++) {
                float denom = fmaxf(sqrtf(b[v] + b0), 1e-12f);
                float val = (a[v] + c0) / denom;
                rp[v] = 1.f / (1.f + __expf(-val));
            }
            *(float4*)&out[q * II + i0 + 4 * lane] = r;
        }
    }
}

extern "C" void kernel_launch(void* const* d_in, const int* in_sizes, int n_in,
                              void* d_out, int out_size) {
    const float* query_feats       = (const float*)d_in[0];
    const float* query_img_feats   = (const float*)d_in[1];
    const float* gallery_img_feats = (const float*)d_in[2];
    const float* bn_gamma          = (const float*)d_in[3];
    const float* bn_beta           = (const float*)d_in[4];
    const float* bn_mean           = (const float*)d_in[5];
    const float* bn_var            = (const float*)d_in[6];
    float* out = (float*)d_out;

    cudaFuncSetAttribute(score_kernel,
                         cudaFuncAttributeMaxDynamicSharedMemorySize, SMEM_SZ);

    prep_kernel<<<64, 256>>>(query_feats, query_img_feats, gallery_img_feats,
                             bn_gamma, bn_beta, bn_mean, bn_var);
    dim3 grid(II / BI, QD / BQ);
    score_kernel<<<grid, 1024, SMEM_SZ>>>(out);
}

// round 9
// speedup vs baseline: 1.2084x; 1.2084x over previous
#include <cuda_runtime.h>
#include <math.h>

#define QD 256    // queries
#define II 2048   // gallery images
#define DD 256    // feature dim

#define BQ 16     // q per block
#define BI 256    // i per block
#define KC 16     // k per tile
#define KPG 128   // k per group (2 groups)
#define NTS 8     // tiles per group
#define UQ 2      // q rows per warp

typedef unsigned long long u64;

// dynamic smem: G tiles only: [group(2)][buf(2)][KC][BI] floats = 64 KB
#define SMEM_SZ (2 * 2 * KC * BI * 4)

// ---- scratch (__device__ globals; no allocation allowed) ----
__device__ __align__(16) u64 d_Cp [QD * DD];  // dup f32x2 of fqn*A   [Q][D]
__device__ __align__(16) u64 d_A2p[QD * DD];  // dup f32x2 of A^2     [Q][D]
__device__ __align__(16) u64 d_ABp[QD * DD];  // dup f32x2 of 2AB     [Q][D]
__device__ float d_GT[DD * II];               // normalized gallery, [D][I]
__device__ float d_c0[QD];
__device__ float d_b0;

// ---------------- packed f32x2 helpers ----------------
__device__ __forceinline__ u64 pack2(float lo, float hi) {
    u64 r;
    asm("mov.b64 %0, {%1, %2};" : "=l"(r) : "f"(lo), "f"(hi));
    return r;
}
__device__ __forceinline__ void unpack2(u64 v, float& lo, float& hi) {
    asm("mov.b64 {%0, %1}, %2;" : "=f"(lo), "=f"(hi) : "l"(v));
}
#define FMA2(acc, a, b) \
    asm("fma.rn.f32x2 %0, %1, %2, %0;" : "+l"(acc) : "l"(a), "l"(b))
#define FMA2R(d, a, b, c) \
    asm("fma.rn.f32x2 %0, %1, %2, %3;" : "=l"(d) : "l"(a), "l"(b), "l"(c))
#define ADD2(acc, v) \
    asm("add.rn.f32x2 %0, %0, %1;" : "+l"(acc) : "l"(v))
#define GBAR(id) \
    asm volatile("bar.sync %0, 256;" :: "r"(id) : "memory")
#define CP16(dst_u32, src_ptr) \
    asm volatile("cp.async.cg.shared.global [%0], [%1], 16;" \
                 :: "r"(dst_u32), "l"(src_ptr) : "memory")
#define CPCOMMIT() asm volatile("cp.async.commit_group;" ::: "memory")
#define CPWAIT1()  asm volatile("cp.async.wait_group 1;" ::: "memory")

__device__ __forceinline__ float warpSum(float v) {
    #pragma unroll
    for (int o = 16; o; o >>= 1) v += __shfl_xor_sync(0xffffffffu, v, o);
    return v;
}

// ---------------- fused prep kernel: 64 blocks x 256 threads ----------------
__global__ __launch_bounds__(256) void prep_kernel(
        const float* __restrict__ qf,
        const float* __restrict__ qi,
        const float* __restrict__ gal,
        const float* __restrict__ gamma,
        const float* __restrict__ beta,
        const float* __restrict__ mean,
        const float* __restrict__ var) {
    const int bx  = blockIdx.x;
    const int tid = threadIdx.x;

    if (bx < 32) {
        // ---- gallery part: normalize + transpose rows i0..i0+63 ----
        __shared__ float sInv[64];
        __shared__ float sT[32][65];
        const int i0 = bx * 64;
        const int w = tid >> 5, lane = tid & 31;

        #pragma unroll
        for (int r = 0; r < 8; r++) {
            int il = w * 8 + r;
            const float4* row = (const float4*)&gal[(il + i0) * DD];
            float4 a = row[lane];
            float4 b = row[lane + 32];
            float ss = a.x*a.x + a.y*a.y + a.z*a.z + a.w*a.w
                     + b.x*b.x + b.y*b.y + b.z*b.z + b.w*b.w;
            ss = warpSum(ss);
            if (lane == 0) sInv[il] = 1.f / fmaxf(sqrtf(ss), 1e-12f);
        }
        __syncthreads();

        for (int dc = 0; dc < DD; dc += 32) {
            #pragma unroll
            for (int it = 0; it < 2; it++) {
                int p  = tid + it * 256;
                int il = p >> 3;
                int kv = p & 7;
                float inv = sInv[il];
                float4 v = *(const float4*)&gal[(i0 + il) * DD + dc + 4 * kv];
                sT[4*kv + 0][il] = v.x * inv;
                sT[4*kv + 1][il] = v.y * inv;
                sT[4*kv + 2][il] = v.z * inv;
                sT[4*kv + 3][il] = v.w * inv;
            }
            __syncthreads();
            #pragma unroll
            for (int half = 0; half < 2; half++) {
                int dl = (tid >> 4) + 16 * half;
                int iv = tid & 15;
                float4 o;
                o.x = sT[dl][4*iv + 0];
                o.y = sT[dl][4*iv + 1];
                o.z = sT[dl][4*iv + 2];
                o.w = sT[dl][4*iv + 3];
                *(float4*)&d_GT[(dc + dl) * II + i0 + 4 * iv] = o;
            }
            __syncthreads();
        }
    } else {
        // ---- query part: warp per query ----
        const int q    = (bx - 32) * 8 + (tid >> 5);
        const int lane = tid & 31;

        float x[8], y[8], istd[8], B[8];
        float xs = 0.f, ys = 0.f;
        #pragma unroll
        for (int j = 0; j < 8; j++) {
            int d = lane + 32 * j;
            x[j] = qf[q * DD + d];
            y[j] = qi[q * DD + d];
            istd[j] = gamma[d] * rsqrtf(var[d] + 1e-5f);
            B[j] = beta[d] - mean[d] * istd[j];
            xs += x[j] * x[j];
            ys += y[j] * y[j];
        }
        xs = warpSum(xs);
        ys = warpSum(ys);
        float xin = 1.f / fmaxf(sqrtf(xs), 1e-12f);
        float yin = 1.f / fmaxf(sqrtf(ys), 1e-12f);

        float A[8], fq[8];
        float fs = 0.f;
        #pragma unroll
        for (int j = 0; j < 8; j++) {
            float xn = x[j] * xin;
            float gate = 1.f / (1.f + __expf(-xn * 5.0f));  // sigmoid(xn/0.2)
            A[j] = gate * istd[j];
            float yn = y[j] * yin;
            fq[j] = yn * A[j] + B[j];
            fs += fq[j] * fq[j];
        }
        fs = warpSum(fs);
        float fin = 1.f / fmaxf(sqrtf(fs), 1e-12f);

        float c0 = 0.f;
        #pragma unroll
        for (int j = 0; j < 8; j++) {
            int d = lane + 32 * j;
            float fqn = fq[j] * fin;
            float cv = fqn * A[j];
            float a2 = A[j] * A[j];
            float ab = 2.f * A[j] * B[j];
            d_Cp [q * DD + d] = pack2(cv, cv);
            d_A2p[q * DD + d] = pack2(a2, a2);
            d_ABp[q * DD + d] = pack2(ab, ab);
            c0 += fqn * B[j];
        }
        c0 = warpSum(c0);
        if (lane == 0) d_c0[q] = c0;

        if (q == 0) {
            float b0 = 0.f;
            #pragma unroll
            for (int j = 0; j < 8; j++) b0 += B[j] * B[j];
            b0 = warpSum(b0);
            if (lane == 0) d_b0 = b0;
        }
    }
}

// ---------------- main scoring kernel ----------------
// grid (II/BI, QD/BQ) = (8, 16) = 128 blocks; 512 threads = 16 warps.
// 2 k-groups x 8 warps; group g covers k in [128g, 128g+128).
// Warp wg owns q rows q0 + 2wg + {0,1}; lane covers i = {4*lane..+3} and
// {128+4*lane..+3} within the 256-wide i tile.
// Coefficients: warp-uniform LDG.128 straight from gmem (no smem, no reuse).
// G: cp.async double-buffered smem tiles, group-private named barriers.
extern __shared__ __align__(16) char dyn_smem[];

__global__ __launch_bounds__(512, 1) void score_kernel(float* __restrict__ out) {
    const int tid  = threadIdx.x;
    const int warp = tid >> 5;
    const int lane = tid & 31;
    const int gsel = warp >> 3;   // k-group 0/1
    const int wg   = warp & 7;    // warp within group -> q rows
    const int gt   = tid & 255;   // thread within group
    const int i0 = blockIdx.x * BI;
    const int q0 = blockIdx.y * BQ;
    const int kbase = gsel * KPG;

    const unsigned sg_base = (unsigned)__cvta_generic_to_shared(dyn_smem);

    u64 s1[UQ][4], s2[UQ][4];
    #pragma unroll
    for (int u = 0; u < UQ; u++)
        #pragma unroll
        for (int v = 0; v < 4; v++) { s1[u][v] = 0ull; s2[u][v] = 0ull; }

    // coefficient base pointers (warp-uniform rows)
    const u64* cBase = d_Cp  + (size_t)(q0 + wg * UQ) * DD + kbase;
    const u64* aBase = d_A2p + (size_t)(q0 + wg * UQ) * DD + kbase;
    const u64* bBase = d_ABp + (size_t)(q0 + wg * UQ) * DD + kbase;

    // async copy of G tile t into buffer (t&1); 4 x 16B per thread
    auto copy_tile = [&](int t) {
        const int buf = t & 1;
        const int k0 = kbase + t * KC;
        #pragma unroll
        for (int j = 0; j < 4; j++) {
            int c = gt + 256 * j;          // 0..1023
            int row = c >> 6;              // 0..15
            int col = (c & 63) * 4;        // float index 0..252
            const float* src = &d_GT[(size_t)(k0 + row) * II + i0 + col];
            unsigned dst = sg_base +
                (unsigned)((((gsel * 2 + buf) * KC + row) * BI + col) * 4);
            CP16(dst, src);
        }
    };

    copy_tile(0); CPCOMMIT();
    copy_tile(1); CPCOMMIT();

    for (int t = 0; t < NTS; t++) {
        const int buf = t & 1;
        CPWAIT1();            // this thread's copies for tile t complete
        GBAR(gsel + 1);       // whole group's copies visible

        const float* gtile = (const float*)(dyn_smem) +
                             (gsel * 2 + buf) * KC * BI;
        const int koff = t * KC;

        #pragma unroll
        for (int p = 0; p < KC / 2; p++) {
            const int kc = 2 * p;
            const float* r0 = gtile + (kc    ) * BI;
            const float* r1 = gtile + (kc + 1) * BI;
            ulonglong2 gA0 = *(const ulonglong2*)&r0[4 * lane];
            ulonglong2 gB0 = *(const ulonglong2*)&r0[128 + 4 * lane];
            ulonglong2 gA1 = *(const ulonglong2*)&r1[4 * lane];
            ulonglong2 gB1 = *(const ulonglong2*)&r1[128 + 4 * lane];
            #pragma unroll
            for (int u = 0; u < UQ; u++) {
                ulonglong2 cp = *(const ulonglong2*)(cBase + u * DD + koff + kc);
                ulonglong2 ap = *(const ulonglong2*)(aBase + u * DD + koff + kc);
                ulonglong2 bp = *(const ulonglong2*)(bBase + u * DD + koff + kc);
                u64 t0, t1, t2, t3;
                // kc
                FMA2(s1[u][0], cp.x, gA0.x);
                FMA2(s1[u][1], cp.x, gA0.y);
                FMA2(s1[u][2], cp.x, gB0.x);
                FMA2(s1[u][3], cp.x, gB0.y);
                FMA2R(t0, ap.x, gA0.x, bp.x); FMA2(s2[u][0], t0, gA0.x);
                FMA2R(t1, ap.x, gA0.y, bp.x); FMA2(s2[u][1], t1, gA0.y);
                FMA2R(t2, ap.x, gB0.x, bp.x); FMA2(s2[u][2], t2, gB0.x);
                FMA2R(t3, ap.x, gB0.y, bp.x); FMA2(s2[u][3], t3, gB0.y);
                // kc+1
                FMA2(s1[u][0], cp.y, gA1.x);
                FMA2(s1[u][1], cp.y, gA1.y);
                FMA2(s1[u][2], cp.y, gB1.x);
                FMA2(s1[u][3], cp.y, gB1.y);
                FMA2R(t0, ap.y, gA1.x, bp.y); FMA2(s2[u][0], t0, gA1.x);
                FMA2R(t1, ap.y, gA1.y, bp.y); FMA2(s2[u][1], t1, gA1.y);
                FMA2R(t2, ap.y, gB1.x, bp.y); FMA2(s2[u][2], t2, gB1.x);
                FMA2R(t3, ap.y, gB1.y, bp.y); FMA2(s2[u][3], t3, gB1.y);
            }
        }

        GBAR(gsel + 1);       // group done reading buf -> safe to overwrite
        if (t + 2 < NTS) copy_tile(t + 2);
        CPCOMMIT();           // commit (possibly empty) to keep group count
    }

    // ---- cross-group reduction: group 1 -> group 0 (two rounds) ----
    ulonglong2* red = (ulonglong2*)dyn_smem;   // 256 thr x 4 x 16B = 16 KB

    __syncthreads();
    if (gsel) {
        #pragma unroll
        for (int u = 0; u < UQ; u++) {
            ulonglong2 va; va.x = s1[u][0]; va.y = s1[u][1];
            ulonglong2 vb; vb.x = s1[u][2]; vb.y = s1[u][3];
            red[gt * 4 + u * 2 + 0] = va;
            red[gt * 4 + u * 2 + 1] = vb;
        }
    }
    __syncthreads();
    if (!gsel) {
        #pragma unroll
        for (int u = 0; u < UQ; u++) {
            ulonglong2 va = red[gt * 4 + u * 2 + 0];
            ulonglong2 vb = red[gt * 4 + u * 2 + 1];
            ADD2(s1[u][0], va.x); ADD2(s1[u][1], va.y);
            ADD2(s1[u][2], vb.x); ADD2(s1[u][3], vb.y);
        }
    }
    __syncthreads();
    if (gsel) {
        #pragma unroll
        for (int u = 0; u < UQ; u++) {
            ulonglong2 va; va.x = s2[u][0]; va.y = s2[u][1];
            ulonglong2 vb; vb.x = s2[u][2]; vb.y = s2[u][3];
            red[gt * 4 + u * 2 + 0] = va;
            red[gt * 4 + u * 2 + 1] = vb;
        }
    }
    __syncthreads();
    if (!gsel) {
        #pragma unroll
        for (int u = 0; u < UQ; u++) {
            ulonglong2 va = red[gt * 4 + u * 2 + 0];
            ulonglong2 vb = red[gt * 4 + u * 2 + 1];
            ADD2(s2[u][0], va.x); ADD2(s2[u][1], va.y);
            ADD2(s2[u][2], vb.x); ADD2(s2[u][3], vb.y);
        }

        // epilogue: score = sigmoid((s1+c0) / max(sqrt(s2+b0), 1e-12))
        const float b0 = d_b0;
        #pragma unroll
        for (int u = 0; u < UQ; u++) {
            int q = q0 + wg * UQ + u;
            float c0 = d_c0[q];
            float a[8], b[8];
            unpack2(s1[u][0], a[0], a[1]);
            unpack2(s1[u][1], a[2], a[3]);
            unpack2(s1[u][2], a[4], a[5]);
            unpack2(s1[u][3], a[6], a[7]);
            unpack2(s2[u][0], b[0], b[1]);
            unpack2(s2[u][1], b[2], b[3]);
            unpack2(s2[u][2], b[4], b[5]);
            unpack2(s2[u][3], b[6], b[7]);
            float4 r0, r1;
            float* rp0 = &r0.x;
            float* rp1 = &r1.x;
            #pragma unroll
            for (int v = 0; v < 4; v++) {
                float d0 = fmaxf(sqrtf(b[v] + b0), 1e-12f);
                rp0[v] = 1.f / (1.f + __expf(-(a[v] + c0) / d0));
                float d1 = fmaxf(sqrtf(b[4 + v] + b0), 1e-12f);
                rp1[v] = 1.f / (1.f + __expf(-(a[4 + v] + c0) / d1));
            }
            *(float4*)&out[(size_t)q * II + i0 + 4 * lane]       = r0;
            *(float4*)&out[(size_t)q * II + i0 + 128 + 4 * lane] = r1;
        }
    }
}

extern "C" void kernel_launch(void* const* d_in, const int* in_sizes, int n_in,
                              void* d_out, int out_size) {
    const float* query_feats       = (const float*)d_in[0];
    const float* query_img_feats   = (const float*)d_in[1];
    const float* gallery_img_feats = (const float*)d_in[2];
    const float* bn_gamma          = (const float*)d_in[3];
    const float* bn_beta           = (const float*)d_in[4];
    const float* bn_mean           = (const float*)d_in[5];
    const float* bn_var            = (const float*)d_in[6];
    float* out = (float*)d_out;

    cudaFuncSetAttribute(score_kernel,
                         cudaFuncAttributeMaxDynamicSharedMemorySize, SMEM_SZ);

    prep_kernel<<<64, 256>>>(query_feats, query_img_feats, gallery_img_feats,
                             bn_gamma, bn_beta, bn_mean, bn_var);
    dim3 grid(II / BI, QD / BQ);
    score_kernel<<<grid, 512, SMEM_SZ>>>(out);
}

// round 11
// speedup vs baseline: 3.1274x; 2.5881x over previous
#include <cuda_runtime.h>
#include <cuda_bf16.h>
#include <math.h>
#include <stdint.h>

#define QD 256    // queries
#define II 2048   // gallery images
#define DD 256    // feature dim

// score tiling
#define TM 128    // i per CTA
#define TN 32     // q per CTA
#define KCH 64    // k per chunk
#define NCH 4     // chunks

// smem: rows padded to 72 bf16 = 144B (16B-aligned, ldmatrix conflict-free)
#define SKB 144
#define GT_BYTES (TM * SKB)            // 18432
#define CT_BYTES (TN * SKB)            // 4608
#define BUF_BYTES (2 * GT_BYTES + 3 * CT_BYTES)  // 50688
#define SMEM_SZ (2 * BUF_BYTES)                  // 101376 (dynamic, opt-in)
#define OFF_G   0
#define OFF_G2  GT_BYTES
#define OFF_C   (2 * GT_BYTES)
#define OFF_A2  (2 * GT_BYTES + CT_BYTES)
#define OFF_AB  (2 * GT_BYTES + 2 * CT_BYTES)

// ---- bf16 operand arrays (natural [row][k] layouts) ----
__device__ __align__(16) __nv_bfloat16 d_Gb [II * DD];  // normalized gallery
__device__ __align__(16) __nv_bfloat16 d_G2b[II * DD];  // g^2
__device__ __align__(16) __nv_bfloat16 d_Cb [QD * DD];  // fqn*A
__device__ __align__(16) __nv_bfloat16 d_A2b[QD * DD];  // A^2
__device__ __align__(16) __nv_bfloat16 d_ABb[QD * DD];  // 2*A*B
__device__ float d_c0[QD];
__device__ float d_b0;

// ---------------- PTX helpers ----------------
#define CP16(dst_u32, src_ptr) \
    asm volatile("cp.async.cg.shared.global [%0], [%1], 16;" \
                 :: "r"(dst_u32), "l"(src_ptr) : "memory")
#define CPCOMMIT() asm volatile("cp.async.commit_group;" ::: "memory")
#define CPWAIT1()  asm volatile("cp.async.wait_group 1;" ::: "memory")

#define LDSM_X4(r0, r1, r2, r3, addr) \
    asm volatile("ldmatrix.sync.aligned.m8n8.x4.shared.b16 {%0,%1,%2,%3}, [%4];" \
                 : "=r"(r0), "=r"(r1), "=r"(r2), "=r"(r3) : "r"(addr))

#define MMA16816(d, a, b0v, b1v) \
    asm volatile("mma.sync.aligned.m16n8k16.row.col.f32.bf16.bf16.f32 " \
                 "{%0,%1,%2,%3}, {%4,%5,%6,%7}, {%8,%9}, {%0,%1,%2,%3};" \
                 : "+f"((d)[0]), "+f"((d)[1]), "+f"((d)[2]), "+f"((d)[3]) \
                 : "r"((a)[0]), "r"((a)[1]), "r"((a)[2]), "r"((a)[3]), \
                   "r"(b0v), "r"(b1v))

__device__ __forceinline__ float warpSum(float v) {
    #pragma unroll
    for (int o = 16; o; o >>= 1) v += __shfl_xor_sync(0xffffffffu, v, o);
    return v;
}

// ---------------- prep kernel: 288 blocks x 256 threads ----------------
// blocks 0..255 : gallery rows (warp per row); 256..287 : queries (warp per q)
__global__ __launch_bounds__(256) void prep_kernel(
        const float* __restrict__ qf,
        const float* __restrict__ qi,
        const float* __restrict__ gal,
        const float* __restrict__ gamma,
        const float* __restrict__ beta,
        const float* __restrict__ mean,
        const float* __restrict__ var) {
    const int bx   = blockIdx.x;
    const int warp = threadIdx.x >> 5;
    const int lane = threadIdx.x & 31;

    if (bx < 256) {
        const int i = bx * 8 + warp;
        const float* row = gal + (size_t)i * DD;
        float x[8];
        float ss = 0.f;
        #pragma unroll
        for (int j = 0; j < 8; j++) {
            x[j] = row[lane + 32 * j];
            ss += x[j] * x[j];
        }
        ss = warpSum(ss);
        float inv = 1.f / fmaxf(sqrtf(ss), 1e-12f);
        #pragma unroll
        for (int j = 0; j < 8; j++) {
            int d = lane + 32 * j;
            float g = x[j] * inv;
            d_Gb [(size_t)i * DD + d] = __float2bfloat16(g);
            d_G2b[(size_t)i * DD + d] = __float2bfloat16(g * g);
        }
    } else {
        const int q = (bx - 256) * 8 + warp;

        float x[8], y[8], istd[8], B[8];
        float xs = 0.f, ys = 0.f;
        #pragma unroll
        for (int j = 0; j < 8; j++) {
            int d = lane + 32 * j;
            x[j] = qf[q * DD + d];
            y[j] = qi[q * DD + d];
            istd[j] = gamma[d] * rsqrtf(var[d] + 1e-5f);
            B[j] = beta[d] - mean[d] * istd[j];
            xs += x[j] * x[j];
            ys += y[j] * y[j];
        }
        xs = warpSum(xs);
        ys = warpSum(ys);
        float xin = 1.f / fmaxf(sqrtf(xs), 1e-12f);
        float yin = 1.f / fmaxf(sqrtf(ys), 1e-12f);

        float A[8], fq[8];
        float fs = 0.f;
        #pragma unroll
        for (int j = 0; j < 8; j++) {
            float xn = x[j] * xin;
            float gate = 1.f / (1.f + __expf(-xn * 5.0f));  // sigmoid(xn/0.2)
            A[j] = gate * istd[j];
            float yn = y[j] * yin;
            fq[j] = yn * A[j] + B[j];
            fs += fq[j] * fq[j];
        }
        fs = warpSum(fs);
        float fin = 1.f / fmaxf(sqrtf(fs), 1e-12f);

        float c0 = 0.f;
        #pragma unroll
        for (int j = 0; j < 8; j++) {
            int d = lane + 32 * j;
            float fqn = fq[j] * fin;
            d_Cb [(size_t)q * DD + d] = __float2bfloat16(fqn * A[j]);
            d_A2b[(size_t)q * DD + d] = __float2bfloat16(A[j] * A[j]);
            d_ABb[(size_t)q * DD + d] = __float2bfloat16(2.f * A[j] * B[j]);
            c0 += fqn * B[j];
        }
        c0 = warpSum(c0);
        if (lane == 0) d_c0[q] = c0;

        if (q == 0) {
            float b0 = 0.f;
            #pragma unroll
            for (int j = 0; j < 8; j++) b0 += B[j] * B[j];
            b0 = warpSum(b0);
            if (lane == 0) d_b0 = b0;
        }
    }
}

// ---------------- HMMA scoring kernel ----------------
// grid (II/TM, QD/TN) = (16, 8) = 128 CTAs; 256 threads = 8 warps (4 i x 2 q).
// Warp tile 32i x 16q: s1/s2 each = 2x2 m16n8 atoms.
// s1 = C.G^T ; s2 = A2.G2^T + AB.G^T.  cp.async double-buffered K chunks.
extern __shared__ __align__(16) char dyn_smem[];

__global__ __launch_bounds__(256) void score_kernel(float* __restrict__ out) {
    const int tid  = threadIdx.x;
    const int warp = tid >> 5;
    const int lane = tid & 31;
    const int wm = warp & 3;       // i block: 32 rows
    const int wn = warp >> 2;      // q block: 16 cols
    const int i0 = blockIdx.x * TM;
    const int q0 = blockIdx.y * TN;

    const uint32_t sb = (uint32_t)__cvta_generic_to_shared(dyn_smem);

    float s1[2][2][4], s2[2][2][4];
    #pragma unroll
    for (int ma = 0; ma < 2; ma++)
        #pragma unroll
        for (int na = 0; na < 2; na++)
            #pragma unroll
            for (int r = 0; r < 4; r++) { s1[ma][na][r] = 0.f; s2[ma][na][r] = 0.f; }

    // ---- cp.async copy of chunk t into buffer (t&1) ----
    auto copy_chunk = [&](int t) {
        const int buf = t & 1;
        const uint32_t base = sb + buf * BUF_BYTES;
        const int kc0 = t * KCH;
        // G / G2: 1024 16B units each, 4 per thread
        #pragma unroll
        for (int j = 0; j < 4; j++) {
            int u = tid + 256 * j;
            int row = u >> 3;            // 0..127
            int c16 = u & 7;             // 16B unit in row
            const size_t src = (size_t)(i0 + row) * DD + kc0 + c16 * 8;
            uint32_t dst = base + row * SKB + c16 * 16;
            CP16(dst + OFF_G,  &d_Gb [src]);
            CP16(dst + OFF_G2, &d_G2b[src]);
        }
        // coeffs: 256 units each, 1 per thread
        {
            int row = tid >> 3;          // 0..31
            int c16 = tid & 7;
            const size_t src = (size_t)(q0 + row) * DD + kc0 + c16 * 8;
            uint32_t dst = base + row * SKB + c16 * 16;
            CP16(dst + OFF_C,  &d_Cb [src]);
            CP16(dst + OFF_A2, &d_A2b[src]);
            CP16(dst + OFF_AB, &d_ABb[src]);
        }
    };

    copy_chunk(0); CPCOMMIT();
    copy_chunk(1); CPCOMMIT();

    // ldmatrix lane-address components
    const int subA = lane >> 3;                       // 0..3
    const int arow = (lane & 7) + (subA & 1) * 8;     // A: +8 rows on odd sub
    const int akof = (subA >> 1) * 16;                // A: +8 k on sub 2,3
    const int brow = (lane & 7) + (subA >> 1) * 8;    // B: +8 rows on sub 2,3
    const int bkof = (subA & 1) * 16;                 // B: +8 k on odd sub

    for (int t = 0; t < NCH; t++) {
        CPWAIT1();
        __syncthreads();

        const uint32_t base = sb + (t & 1) * BUF_BYTES;
        const uint32_t gA0 = base + OFF_G  + (wm * 32 + arow) * SKB + akof;
        const uint32_t gA1 = gA0 + 16 * SKB;
        const uint32_t g2A0 = base + OFF_G2 + (wm * 32 + arow) * SKB + akof;
        const uint32_t g2A1 = g2A0 + 16 * SKB;
        const uint32_t cB  = base + OFF_C  + (wn * 16 + brow) * SKB + bkof;
        const uint32_t a2B = base + OFF_A2 + (wn * 16 + brow) * SKB + bkof;
        const uint32_t abB = base + OFF_AB + (wn * 16 + brow) * SKB + bkof;

        #pragma unroll
        for (int ks = 0; ks < 4; ks++) {
            const uint32_t kb = ks * 32;   // 16 bf16 per step

            uint32_t aG[2][4], aG2[2][4], bC[4], bA2[4], bAB[4];
            LDSM_X4(aG[0][0],  aG[0][1],  aG[0][2],  aG[0][3],  gA0  + kb);
            LDSM_X4(aG[1][0],  aG[1][1],  aG[1][2],  aG[1][3],  gA1  + kb);
            LDSM_X4(aG2[0][0], aG2[0][1], aG2[0][2], aG2[0][3], g2A0 + kb);
            LDSM_X4(aG2[1][0], aG2[1][1], aG2[1][2], aG2[1][3], g2A1 + kb);
            LDSM_X4(bC[0],  bC[1],  bC[2],  bC[3],  cB  + kb);
            LDSM_X4(bA2[0], bA2[1], bA2[2], bA2[3], a2B + kb);
            LDSM_X4(bAB[0], bAB[1], bAB[2], bAB[3], abB + kb);

            #pragma unroll
            for (int ma = 0; ma < 2; ma++) {
                #pragma unroll
                for (int na = 0; na < 2; na++) {
                    MMA16816(s1[ma][na], aG[ma],  bC[2*na],  bC[2*na+1]);
                    MMA16816(s2[ma][na], aG2[ma], bA2[2*na], bA2[2*na+1]);
                    MMA16816(s2[ma][na], aG[ma],  bAB[2*na], bAB[2*na+1]);
                }
            }
        }

        __syncthreads();
        if (t + 2 < NCH) copy_chunk(t + 2);
        CPCOMMIT();
    }

    // ---- epilogue ----
    // c-fragment: c0,c1 -> row = lane>>2, cols 2*(lane&3)+{0,1}; c2,c3 -> row+8
    const float b0 = d_b0;
    const int rbase = lane >> 2;
    const int cbase = 2 * (lane & 3);
    #pragma unroll
    for (int ma = 0; ma < 2; ma++) {
        #pragma unroll
        for (int na = 0; na < 2; na++) {
            #pragma unroll
            for (int r = 0; r < 4; r++) {
                int i = i0 + wm * 32 + ma * 16 + rbase + (r >> 1) * 8;
                int q = q0 + wn * 16 + na * 8 + cbase + (r & 1);
                float v1 = s1[ma][na][r] + d_c0[q];
                float v2 = s2[ma][na][r] + b0;
                float val = v1 * rsqrtf(fmaxf(v2, 1e-24f));
                out[(size_t)q * II + i] = 1.f / (1.f + __expf(-val));
            }
        }
    }
}

extern "C" void kernel_launch(void* const* d_in, const int* in_sizes, int n_in,
                              void* d_out, int out_size) {
    const float* query_feats       = (const float*)d_in[0];
    const float* query_img_feats   = (const float*)d_in[1];
    const float* gallery_img_feats = (const float*)d_in[2];
    const float* bn_gamma          = (const float*)d_in[3];
    const float* bn_beta           = (const float*)d_in[4];
    const float* bn_mean           = (const float*)d_in[5];
    const float* bn_var            = (const float*)d_in[6];
    float* out = (float*)d_out;

    cudaFuncSetAttribute(score_kernel,
                         cudaFuncAttributeMaxDynamicSharedMemorySize, SMEM_SZ);

    prep_kernel<<<288, 256>>>(query_feats, query_img_feats, gallery_img_feats,
                              bn_gamma, bn_beta, bn_mean, bn_var);
    dim3 grid(II / TM, QD / TN);
    score_kernel<<<grid, 256, SMEM_SZ>>>(out);
}

// round 12
// speedup vs baseline: 3.1746x; 1.0151x over previous
#include <cuda_runtime.h>
#include <cuda_bf16.h>
#include <math.h>
#include <stdint.h>

#define QD 256    // queries
#define II 2048   // gallery images
#define DD 256    // feature dim

// score tiling
#define TM 128    // i per CTA
#define TN 32     // q per CTA
#define KCH 64    // k per chunk
#define NCH 4     // chunks

// smem: rows padded to 72 bf16 = 144B (16B-aligned, ldmatrix conflict-free)
#define SKB 144
#define GT_BYTES (TM * SKB)            // 18432
#define CT_BYTES (TN * SKB)            // 4608
#define BUF_BYTES (2 * GT_BYTES + 3 * CT_BYTES)  // 50688
#define SMEM_SZ (2 * BUF_BYTES)                  // 101376 (dynamic, opt-in)
#define OFF_G   0
#define OFF_G2  GT_BYTES
#define OFF_C   (2 * GT_BYTES)
#define OFF_A2  (2 * GT_BYTES + CT_BYTES)
#define OFF_AB  (2 * GT_BYTES + 2 * CT_BYTES)

// ---- bf16 operand arrays (natural [row][k] layouts) ----
__device__ __align__(16) __nv_bfloat16 d_Gb [II * DD];  // normalized gallery
__device__ __align__(16) __nv_bfloat16 d_G2b[II * DD];  // g^2
__device__ __align__(16) __nv_bfloat16 d_Cb [QD * DD];  // fqn*A
__device__ __align__(16) __nv_bfloat16 d_A2b[QD * DD];  // A^2
__device__ __align__(16) __nv_bfloat16 d_ABb[QD * DD];  // 2*A*B
__device__ float d_c0[QD];
__device__ float d_b0;

// ---------------- PTX helpers ----------------
#define CP16(dst_u32, src_ptr) \
    asm volatile("cp.async.cg.shared.global [%0], [%1], 16;" \
                 :: "r"(dst_u32), "l"(src_ptr) : "memory")
#define CPCOMMIT() asm volatile("cp.async.commit_group;" ::: "memory")
#define CPWAIT1()  asm volatile("cp.async.wait_group 1;" ::: "memory")

#define LDSM_X4(r0, r1, r2, r3, addr) \
    asm volatile("ldmatrix.sync.aligned.m8n8.x4.shared.b16 {%0,%1,%2,%3}, [%4];" \
                 : "=r"(r0), "=r"(r1), "=r"(r2), "=r"(r3) : "r"(addr))

#define MMA16816(d, a, b0v, b1v) \
    asm volatile("mma.sync.aligned.m16n8k16.row.col.f32.bf16.bf16.f32 " \
                 "{%0,%1,%2,%3}, {%4,%5,%6,%7}, {%8,%9}, {%0,%1,%2,%3};" \
                 : "+f"((d)[0]), "+f"((d)[1]), "+f"((d)[2]), "+f"((d)[3]) \
                 : "r"((a)[0]), "r"((a)[1]), "r"((a)[2]), "r"((a)[3]), \
                   "r"(b0v), "r"(b1v))

__device__ __forceinline__ float warpSum(float v) {
    #pragma unroll
    for (int o = 16; o; o >>= 1) v += __shfl_xor_sync(0xffffffffu, v, o);
    return v;
}

// ---------------- prep kernel: 288 blocks x 256 threads ----------------
// blocks 0..255 : gallery rows (warp per row); 256..287 : queries (warp per q)
__global__ __launch_bounds__(256) void prep_kernel(
        const float* __restrict__ qf,
        const float* __restrict__ qi,
        const float* __restrict__ gal,
        const float* __restrict__ gamma,
        const float* __restrict__ beta,
        const float* __restrict__ mean,
        const float* __restrict__ var) {
    const int bx   = blockIdx.x;
    const int warp = threadIdx.x >> 5;
    const int lane = threadIdx.x & 31;

    if (bx < 256) {
        const int i = bx * 8 + warp;
        const float* row = gal + (size_t)i * DD;
        float x[8];
        float ss = 0.f;
        #pragma unroll
        for (int j = 0; j < 8; j++) {
            x[j] = row[lane + 32 * j];
            ss += x[j] * x[j];
        }
        ss = warpSum(ss);
        float inv = 1.f / fmaxf(sqrtf(ss), 1e-12f);
        #pragma unroll
        for (int j = 0; j < 8; j++) {
            int d = lane + 32 * j;
            float g = x[j] * inv;
            d_Gb [(size_t)i * DD + d] = __float2bfloat16(g);
            d_G2b[(size_t)i * DD + d] = __float2bfloat16(g * g);
        }
    } else {
        const int q = (bx - 256) * 8 + warp;

        float x[8], y[8], istd[8], B[8];
        float xs = 0.f, ys = 0.f;
        #pragma unroll
        for (int j = 0; j < 8; j++) {
            int d = lane + 32 * j;
            x[j] = qf[q * DD + d];
            y[j] = qi[q * DD + d];
            istd[j] = gamma[d] * rsqrtf(var[d] + 1e-5f);
            B[j] = beta[d] - mean[d] * istd[j];
            xs += x[j] * x[j];
            ys += y[j] * y[j];
        }
        xs = warpSum(xs);
        ys = warpSum(ys);
        float xin = 1.f / fmaxf(sqrtf(xs), 1e-12f);
        float yin = 1.f / fmaxf(sqrtf(ys), 1e-12f);

        float A[8], fq[8];
        float fs = 0.f;
        #pragma unroll
        for (int j = 0; j < 8; j++) {
            float xn = x[j] * xin;
            float gate = 1.f / (1.f + __expf(-xn * 5.0f));  // sigmoid(xn/0.2)
            A[j] = gate * istd[j];
            float yn = y[j] * yin;
            fq[j] = yn * A[j] + B[j];
            fs += fq[j] * fq[j];
        }
        fs = warpSum(fs);
        float fin = 1.f / fmaxf(sqrtf(fs), 1e-12f);

        float c0 = 0.f;
        #pragma unroll
        for (int j = 0; j < 8; j++) {
            int d = lane + 32 * j;
            float fqn = fq[j] * fin;
            d_Cb [(size_t)q * DD + d] = __float2bfloat16(fqn * A[j]);
            d_A2b[(size_t)q * DD + d] = __float2bfloat16(A[j] * A[j]);
            d_ABb[(size_t)q * DD + d] = __float2bfloat16(2.f * A[j] * B[j]);
            c0 += fqn * B[j];
        }
        c0 = warpSum(c0);
        if (lane == 0) d_c0[q] = c0;

        if (q == 0) {
            float b0 = 0.f;
            #pragma unroll
            for (int j = 0; j < 8; j++) b0 += B[j] * B[j];
            b0 = warpSum(b0);
            if (lane == 0) d_b0 = b0;
        }
    }
}

// ---------------- HMMA scoring kernel ----------------
// grid (II/TM, QD/TN) = (16, 8) = 128 CTAs; 512 threads = 16 warps (4 i x 4 q).
// Warp tile 32i x 8q: s1/s2 each = 2 m16n8 atoms.
// s1 = C.G^T ; s2 = A2.G2^T + AB.G^T.  cp.async double-buffered K chunks.
extern __shared__ __align__(16) char dyn_smem[];

__global__ __launch_bounds__(512) void score_kernel(float* __restrict__ out) {
    const int tid  = threadIdx.x;
    const int warp = tid >> 5;
    const int lane = tid & 31;
    const int wm = warp & 3;       // i block: 32 rows
    const int wn = warp >> 2;      // q block: 8 cols
    const int i0 = blockIdx.x * TM;
    const int q0 = blockIdx.y * TN;

    const uint32_t sb = (uint32_t)__cvta_generic_to_shared(dyn_smem);

    float s1[2][4], s2[2][4];
    #pragma unroll
    for (int ma = 0; ma < 2; ma++)
        #pragma unroll
        for (int r = 0; r < 4; r++) { s1[ma][r] = 0.f; s2[ma][r] = 0.f; }

    // ---- cp.async copy of chunk t into buffer (t&1) ----
    auto copy_chunk = [&](int t) {
        const int buf = t & 1;
        const uint32_t base = sb + buf * BUF_BYTES;
        const int kc0 = t * KCH;
        // G / G2: 1024 16B units each, 2 per thread
        #pragma unroll
        for (int j = 0; j < 2; j++) {
            int u = tid + 512 * j;
            int row = u >> 3;            // 0..127
            int c16 = u & 7;             // 16B unit in row
            const size_t src = (size_t)(i0 + row) * DD + kc0 + c16 * 8;
            uint32_t dst = base + row * SKB + c16 * 16;
            CP16(dst + OFF_G,  &d_Gb [src]);
            CP16(dst + OFF_G2, &d_G2b[src]);
        }
        // coeffs: 256 units each, first 256 threads
        if (tid < 256) {
            int row = tid >> 3;          // 0..31
            int c16 = tid & 7;
            const size_t src = (size_t)(q0 + row) * DD + kc0 + c16 * 8;
            uint32_t dst = base + row * SKB + c16 * 16;
            CP16(dst + OFF_C,  &d_Cb [src]);
            CP16(dst + OFF_A2, &d_A2b[src]);
            CP16(dst + OFF_AB, &d_ABb[src]);
        }
    };

    copy_chunk(0); CPCOMMIT();
    copy_chunk(1); CPCOMMIT();

    // ldmatrix lane-address components
    const int subA = lane >> 3;                       // 0..3
    const int arow = (lane & 7) + (subA & 1) * 8;     // A: rows 0..15
    const int akof = (subA >> 1) * 16;                // A: +8 k on sub 2,3
    // B: x4 covers q(8) x k(32): lane&7 -> q row, lane>>3 -> 8k block
    const int brow = lane & 7;
    const int bkof = (lane >> 3) * 16;

    for (int t = 0; t < NCH; t++) {
        CPWAIT1();
        __syncthreads();

        const uint32_t base = sb + (t & 1) * BUF_BYTES;
        const uint32_t gA0  = base + OFF_G  + (wm * 32 + arow) * SKB + akof;
        const uint32_t gA1  = gA0 + 16 * SKB;
        const uint32_t g2A0 = base + OFF_G2 + (wm * 32 + arow) * SKB + akof;
        const uint32_t g2A1 = g2A0 + 16 * SKB;
        const uint32_t cB   = base + OFF_C  + (wn * 8 + brow) * SKB + bkof;
        const uint32_t a2B  = base + OFF_A2 + (wn * 8 + brow) * SKB + bkof;
        const uint32_t abB  = base + OFF_AB + (wn * 8 + brow) * SKB + bkof;

        #pragma unroll
        for (int p = 0; p < 2; p++) {              // k-step pairs (k32 each)
            const uint32_t pb = p * 64;            // 32 bf16 = 64 B

            uint32_t bC[4], bA2[4], bAB[4];
            LDSM_X4(bC[0],  bC[1],  bC[2],  bC[3],  cB  + pb);
            LDSM_X4(bA2[0], bA2[1], bA2[2], bA2[3], a2B + pb);
            LDSM_X4(bAB[0], bAB[1], bAB[2], bAB[3], abB + pb);

            #pragma unroll
            for (int e = 0; e < 2; e++) {          // k16 steps within pair
                const uint32_t kb = pb + e * 32;
                uint32_t aG[2][4], aG2[2][4];
                LDSM_X4(aG[0][0],  aG[0][1],  aG[0][2],  aG[0][3],  gA0  + kb);
                LDSM_X4(aG[1][0],  aG[1][1],  aG[1][2],  aG[1][3],  gA1  + kb);
                LDSM_X4(aG2[0][0], aG2[0][1], aG2[0][2], aG2[0][3], g2A0 + kb);
                LDSM_X4(aG2[1][0], aG2[1][1], aG2[1][2], aG2[1][3], g2A1 + kb);

                #pragma unroll
                for (int ma = 0; ma < 2; ma++) {
                    MMA16816(s1[ma], aG[ma],  bC[2*e],  bC[2*e+1]);
                    MMA16816(s2[ma], aG2[ma], bA2[2*e], bA2[2*e+1]);
                    MMA16816(s2[ma], aG[ma],  bAB[2*e], bAB[2*e+1]);
                }
            }
        }

        __syncthreads();
        if (t + 2 < NCH) copy_chunk(t + 2);
        CPCOMMIT();
    }

    // ---- epilogue ----
    // c-fragment: c0,c1 -> row = lane>>2, cols 2*(lane&3)+{0,1}; c2,c3 -> row+8
    const float b0 = d_b0;
    const int rbase = lane >> 2;
    const int cbase = 2 * (lane & 3);
    #pragma unroll
    for (int ma = 0; ma < 2; ma++) {
        #pragma unroll
        for (int r = 0; r < 4; r++) {
            int i = i0 + wm * 32 + ma * 16 + rbase + (r >> 1) * 8;
            int q = q0 + wn * 8 + cbase + (r & 1);
            float v1 = s1[ma][r] + d_c0[q];
            float v2 = s2[ma][r] + b0;
            float val = v1 * rsqrtf(fmaxf(v2, 1e-24f));
            out[(size_t)q * II + i] = 1.f / (1.f + __expf(-val));
        }
    }
}

extern "C" void kernel_launch(void* const* d_in, const int* in_sizes, int n_in,
                              void* d_out, int out_size) {
    const float* query_feats       = (const float*)d_in[0];
    const float* query_img_feats   = (const float*)d_in[1];
    const float* gallery_img_feats = (const float*)d_in[2];
    const float* bn_gamma          = (const float*)d_in[3];
    const float* bn_beta           = (const float*)d_in[4];
    const float* bn_mean           = (const float*)d_in[5];
    const float* bn_var            = (const float*)d_in[6];
    float* out = (float*)d_out;

    cudaFuncSetAttribute(score_kernel,
                         cudaFuncAttributeMaxDynamicSharedMemorySize, SMEM_SZ);

    prep_kernel<<<288, 256>>>(query_feats, query_img_feats, gallery_img_feats,
                              bn_gamma, bn_beta, bn_mean, bn_var);
    dim3 grid(II / TM, QD / TN);
    score_kernel<<<grid, 512, SMEM_SZ>>>(out);
}

// round 13
// speedup vs baseline: 3.1814x; 1.0022x over previous
#include <cuda_runtime.h>
#include <cuda_bf16.h>
#include <math.h>
#include <stdint.h>

#define QD 256    // queries
#define II 2048   // gallery images
#define DD 256    // feature dim

#define TM 128    // i per CTA
#define TN 32     // q per CTA

// smem rows: 256 bf16 = 512 B + 16 pad = 528 B (16B-aligned; 8-row ldmatrix
// phases hit banks 4r mod 32 -> conflict-free)
#define SKB 528
#define HDR 256                         // c0[32] floats + b0
#define OFF_G  HDR
#define OFF_C  (OFF_G + TM * SKB)       // 67840
#define OFF_A2 (OFF_C + TN * SKB)       // 84736
#define OFF_AB (OFF_A2 + TN * SKB)      // 101632
#define SMEM_SZ (OFF_AB + TN * SKB)     // 118528 B (< 227 KB; opt-in)

// ---------------- PTX helpers ----------------
#define LDSM_X4(r0, r1, r2, r3, addr) \
    asm volatile("ldmatrix.sync.aligned.m8n8.x4.shared.b16 {%0,%1,%2,%3}, [%4];" \
                 : "=r"(r0), "=r"(r1), "=r"(r2), "=r"(r3) : "r"(addr))

#define MMA16816(d, a, b0v, b1v) \
    asm volatile("mma.sync.aligned.m16n8k16.row.col.f32.bf16.bf16.f32 " \
                 "{%0,%1,%2,%3}, {%4,%5,%6,%7}, {%8,%9}, {%0,%1,%2,%3};" \
                 : "+f"((d)[0]), "+f"((d)[1]), "+f"((d)[2]), "+f"((d)[3]) \
                 : "r"((a)[0]), "r"((a)[1]), "r"((a)[2]), "r"((a)[3]), \
                   "r"(b0v), "r"(b1v))

#define SQR_BF16X2(d, a) \
    asm("mul.bf16x2 %0, %1, %1;" : "=r"(d) : "r"(a))

__device__ __forceinline__ float warpSum(float v) {
    #pragma unroll
    for (int o = 16; o; o >>= 1) v += __shfl_xor_sync(0xffffffffu, v, o);
    return v;
}

// pack 8 floats -> 8 bf16 in a uint4
__device__ __forceinline__ uint4 pack8_bf16(const float* f) {
    union { __nv_bfloat16 h[8]; uint4 u; } cv;
    #pragma unroll
    for (int j = 0; j < 8; j++) cv.h[j] = __float2bfloat16(f[j]);
    return cv.u;
}

// ---------------- fused scoring kernel ----------------
// grid (II/TM, QD/TN) = (16, 8) = 128 CTAs; 512 threads = 16 warps (4 i x 4 q).
// Phase 1: normalize gallery rows i0..i0+127 (8 rows/warp), bf16 -> smem G.
// Phase 2: query chain for q0..q0+31 (2 rows/warp), bf16 C/A2/AB -> smem.
// Phase 3: straight HMMA over K=256 (no barriers). G2 fragments derived by
//          squaring G fragments in registers (mul.bf16x2).
// s1 = C.G^T ; s2 = A2.G2^T + AB.G^T ; score = sigmoid((s1+c0)/sqrt(s2+b0)).
extern __shared__ __align__(16) char dyn_smem[];

__global__ __launch_bounds__(512) void score_kernel(
        float* __restrict__ out,
        const float* __restrict__ qf,
        const float* __restrict__ qi,
        const float* __restrict__ gal,
        const float* __restrict__ gamma,
        const float* __restrict__ beta,
        const float* __restrict__ mean,
        const float* __restrict__ var) {
    const int tid  = threadIdx.x;
    const int warp = tid >> 5;
    const int lane = tid & 31;
    const int wm = warp & 3;       // i block (32 rows)
    const int wn = warp >> 2;      // q block (8 cols)
    const int i0 = blockIdx.x * TM;
    const int q0 = blockIdx.y * TN;

    const uint32_t sb = (uint32_t)__cvta_generic_to_shared(dyn_smem);
    float* sc0 = (float*)dyn_smem;          // c0[32]
    float* sb0 = (float*)(dyn_smem + 128);  // b0

    // ---- phase 1: gallery rows (lane owns d = 8*lane .. 8*lane+7) ----
    #pragma unroll
    for (int rb = 0; rb < 8; rb += 4) {
        float4 v[4][2];
        #pragma unroll
        for (int r = 0; r < 4; r++) {
            int row = warp * 8 + rb + r;
            const float4* src = (const float4*)&gal[(size_t)(i0 + row) * DD + lane * 8];
            v[r][0] = src[0];
            v[r][1] = src[1];
        }
        #pragma unroll
        for (int r = 0; r < 4; r++) {
            int row = warp * 8 + rb + r;
            const float* f = (const float*)&v[r][0];
            float ss = 0.f;
            #pragma unroll
            for (int j = 0; j < 8; j++) ss += f[j] * f[j];
            ss = warpSum(ss);
            float inv = 1.f / fmaxf(sqrtf(ss), 1e-12f);
            float g[8];
            #pragma unroll
            for (int j = 0; j < 8; j++) g[j] = f[j] * inv;
            *(uint4*)(dyn_smem + OFF_G + row * SKB + lane * 16) = pack8_bf16(g);
        }
    }

    // ---- phase 2: query chain (2 rows per warp; lane owns d = 8*lane..+7) ----
    {
        const float4* gv4 = (const float4*)&gamma[lane * 8];
        const float4* bv4 = (const float4*)&beta [lane * 8];
        const float4* mv4 = (const float4*)&mean [lane * 8];
        const float4* vv4 = (const float4*)&var  [lane * 8];
        float ga[8], be[8], me[8], va[8];
        *(float4*)&ga[0] = gv4[0]; *(float4*)&ga[4] = gv4[1];
        *(float4*)&be[0] = bv4[0]; *(float4*)&be[4] = bv4[1];
        *(float4*)&me[0] = mv4[0]; *(float4*)&me[4] = mv4[1];
        *(float4*)&va[0] = vv4[0]; *(float4*)&va[4] = vv4[1];

        float istd[8], B[8];
        #pragma unroll
        for (int j = 0; j < 8; j++) {
            istd[j] = ga[j] * rsqrtf(va[j] + 1e-5f);
            B[j] = be[j] - me[j] * istd[j];
        }

        #pragma unroll
        for (int r = 0; r < 2; r++) {
            int ql = warp * 2 + r;         // 0..31
            int q  = q0 + ql;
            float x[8], y[8];
            {
                const float4* xs4 = (const float4*)&qf[(size_t)q * DD + lane * 8];
                const float4* ys4 = (const float4*)&qi[(size_t)q * DD + lane * 8];
                *(float4*)&x[0] = xs4[0]; *(float4*)&x[4] = xs4[1];
                *(float4*)&y[0] = ys4[0]; *(float4*)&y[4] = ys4[1];
            }
            float xs = 0.f, ys = 0.f;
            #pragma unroll
            for (int j = 0; j < 8; j++) { xs += x[j] * x[j]; ys += y[j] * y[j]; }
            xs = warpSum(xs);
            ys = warpSum(ys);
            float xin = 1.f / fmaxf(sqrtf(xs), 1e-12f);
            float yin = 1.f / fmaxf(sqrtf(ys), 1e-12f);

            float A[8], fq[8];
            float fs = 0.f;
            #pragma unroll
            for (int j = 0; j < 8; j++) {
                float xn = x[j] * xin;
                float gate = 1.f / (1.f + __expf(-xn * 5.0f));  // sigmoid(xn/0.2)
                A[j] = gate * istd[j];
                float yn = y[j] * yin;
                fq[j] = yn * A[j] + B[j];
                fs += fq[j] * fq[j];
            }
            fs = warpSum(fs);
            float fin = 1.f / fmaxf(sqrtf(fs), 1e-12f);

            float Cv[8], A2v[8], ABv[8];
            float c0 = 0.f;
            #pragma unroll
            for (int j = 0; j < 8; j++) {
                float fqn = fq[j] * fin;
                Cv[j]  = fqn * A[j];
                A2v[j] = A[j] * A[j];
                ABv[j] = 2.f * A[j] * B[j];
                c0 += fqn * B[j];
            }
            c0 = warpSum(c0);
            if (lane == 0) sc0[ql] = c0;

            *(uint4*)(dyn_smem + OFF_C  + ql * SKB + lane * 16) = pack8_bf16(Cv);
            *(uint4*)(dyn_smem + OFF_A2 + ql * SKB + lane * 16) = pack8_bf16(A2v);
            *(uint4*)(dyn_smem + OFF_AB + ql * SKB + lane * 16) = pack8_bf16(ABv);

            if (ql == 0) {   // warp 0 only (uniform branch)
                float b0 = 0.f;
                #pragma unroll
                for (int j = 0; j < 8; j++) b0 += B[j] * B[j];
                b0 = warpSum(b0);
                if (lane == 0) sb0[0] = b0;
            }
        }
    }

    __syncthreads();

    // ---- phase 3: straight HMMA over K = 256, no barriers ----
    float s1[2][4], s2[2][4];
    #pragma unroll
    for (int ma = 0; ma < 2; ma++)
        #pragma unroll
        for (int r = 0; r < 4; r++) { s1[ma][r] = 0.f; s2[ma][r] = 0.f; }

    const int subA = lane >> 3;
    const int arow = (lane & 7) + (subA & 1) * 8;
    const int akof = (subA >> 1) * 16;
    const int brow = lane & 7;
    const int bkof = (lane >> 3) * 16;

    const uint32_t gA0 = sb + OFF_G  + (wm * 32 + arow) * SKB + akof;
    const uint32_t gA1 = gA0 + 16 * SKB;
    const uint32_t cB  = sb + OFF_C  + (wn * 8 + brow) * SKB + bkof;
    const uint32_t a2B = sb + OFF_A2 + (wn * 8 + brow) * SKB + bkof;
    const uint32_t abB = sb + OFF_AB + (wn * 8 + brow) * SKB + bkof;

    #pragma unroll
    for (int p = 0; p < 8; p++) {              // 8 pairs of k16 (k32 each)
        const uint32_t pb = p * 64;            // 32 bf16 = 64 B

        uint32_t bC[4], bA2[4], bAB[4];
        LDSM_X4(bC[0],  bC[1],  bC[2],  bC[3],  cB  + pb);
        LDSM_X4(bA2[0], bA2[1], bA2[2], bA2[3], a2B + pb);
        LDSM_X4(bAB[0], bAB[1], bAB[2], bAB[3], abB + pb);

        #pragma unroll
        for (int e = 0; e < 2; e++) {
            const uint32_t kb = pb + e * 32;
            uint32_t aG[2][4], aG2[2][4];
            LDSM_X4(aG[0][0], aG[0][1], aG[0][2], aG[0][3], gA0 + kb);
            LDSM_X4(aG[1][0], aG[1][1], aG[1][2], aG[1][3], gA1 + kb);
            #pragma unroll
            for (int ma = 0; ma < 2; ma++)
                #pragma unroll
                for (int r = 0; r < 4; r++)
                    SQR_BF16X2(aG2[ma][r], aG[ma][r]);

            #pragma unroll
            for (int ma = 0; ma < 2; ma++) {
                MMA16816(s1[ma], aG[ma],  bC[2*e],  bC[2*e+1]);
                MMA16816(s2[ma], aG2[ma], bA2[2*e], bA2[2*e+1]);
                MMA16816(s2[ma], aG[ma],  bAB[2*e], bAB[2*e+1]);
            }
        }
    }

    // ---- epilogue ----
    const float b0 = sb0[0];
    const int rbase = lane >> 2;
    const int cbase = 2 * (lane & 3);
    #pragma unroll
    for (int ma = 0; ma < 2; ma++) {
        #pragma unroll
        for (int r = 0; r < 4; r++) {
            int i  = i0 + wm * 32 + ma * 16 + rbase + (r >> 1) * 8;
            int ql = wn * 8 + cbase + (r & 1);
            float v1 = s1[ma][r] + sc0[ql];
            float v2 = s2[ma][r] + b0;
            float val = v1 * rsqrtf(fmaxf(v2, 1e-24f));
            out[(size_t)(q0 + ql) * II + i] = 1.f / (1.f + __expf(-val));
        }
    }
}

extern "C" void kernel_launch(void* const* d_in, const int* in_sizes, int n_in,
                              void* d_out, int out_size) {
    const float* query_feats       = (const float*)d_in[0];
    const float* query_img_feats   = (const float*)d_in[1];
    const float* gallery_img_feats = (const float*)d_in[2];
    const float* bn_gamma          = (const float*)d_in[3];
    const float* bn_beta           = (const float*)d_in[4];
    const float* bn_mean           = (const float*)d_in[5];
    const float* bn_var            = (const float*)d_in[6];
    float* out = (float*)d_out;

    cudaFuncSetAttribute(score_kernel,
                         cudaFuncAttributeMaxDynamicSharedMemorySize, SMEM_SZ);

    dim3 grid(II / TM, QD / TN);
    score_kernel<<<grid, 512, SMEM_SZ>>>(out, query_feats, query_img_feats,
                                         gallery_img_feats, bn_gamma, bn_beta,
                                         bn_mean, bn_var);
}

// round 14
// speedup vs baseline: 3.5409x; 1.1130x over previous
#include <cuda_runtime.h>
#include <cuda_bf16.h>
#include <math.h>
#include <stdint.h>

#define QD 256    // queries
#define II 2048   // gallery images
#define DD 256    // feature dim

#define TM 128    // i per CTA
#define TN 32     // q per CTA

// smem rows: 256 bf16 = 512 B + 16 pad = 528 B; 528 = 132 banks ≡ 4 (mod 32):
// each 8-row ldmatrix phase covers all 32 banks exactly once -> conflict-free.
#define SKB 528
#define OFF_G  0
#define OFF_C  (OFF_G + TM * SKB)       // 67584
#define OFF_A2 (OFF_C + TN * SKB)       // 84480
#define OFF_AB (OFF_A2 + TN * SKB)      // 101376
#define SMEM_SZ (OFF_AB + TN * SKB)     // 118272 B (opt-in)

// ---- bf16 operand arrays (natural [row][k] layouts) ----
__device__ __align__(16) __nv_bfloat16 d_Gb [II * DD];  // normalized gallery
__device__ __align__(16) __nv_bfloat16 d_Cb [QD * DD];  // fqn*A
__device__ __align__(16) __nv_bfloat16 d_A2b[QD * DD];  // A^2
__device__ __align__(16) __nv_bfloat16 d_ABb[QD * DD];  // 2*A*B
__device__ float d_c0[QD];
__device__ float d_b0;

// ---------------- PTX helpers ----------------
#define CP16(dst_u32, src_ptr) \
    asm volatile("cp.async.cg.shared.global [%0], [%1], 16;" \
                 :: "r"(dst_u32), "l"(src_ptr) : "memory")
#define CPCOMMIT() asm volatile("cp.async.commit_group;" ::: "memory")
#define CPWAIT0()  asm volatile("cp.async.wait_group 0;" ::: "memory")

#define LDSM_X4(r0, r1, r2, r3, addr) \
    asm volatile("ldmatrix.sync.aligned.m8n8.x4.shared.b16 {%0,%1,%2,%3}, [%4];" \
                 : "=r"(r0), "=r"(r1), "=r"(r2), "=r"(r3) : "r"(addr))

#define MMA16816(d, a, b0v, b1v) \
    asm volatile("mma.sync.aligned.m16n8k16.row.col.f32.bf16.bf16.f32 " \
                 "{%0,%1,%2,%3}, {%4,%5,%6,%7}, {%8,%9}, {%0,%1,%2,%3};" \
                 : "+f"((d)[0]), "+f"((d)[1]), "+f"((d)[2]), "+f"((d)[3]) \
                 : "r"((a)[0]), "r"((a)[1]), "r"((a)[2]), "r"((a)[3]), \
                   "r"(b0v), "r"(b1v))

#define SQR_BF16X2(d, a) \
    asm("mul.bf16x2 %0, %1, %1;" : "=r"(d) : "r"(a))

// pack two fp32 -> one bf16x2 register (no union, no local memory)
#define CVT2(dst, lo, hi) \
    asm("cvt.rn.bf16x2.f32 %0, %1, %2;" : "=r"(dst) : "f"(hi), "f"(lo))

__device__ __forceinline__ float warpSum(float v) {
    #pragma unroll
    for (int o = 16; o; o >>= 1) v += __shfl_xor_sync(0xffffffffu, v, o);
    return v;
}

// pack 8 floats (lane-owned contiguous d) into uint4 of bf16x2
__device__ __forceinline__ uint4 pack8(const float* f) {
    uint4 u;
    CVT2(u.x, f[0], f[1]);
    CVT2(u.y, f[2], f[3]);
    CVT2(u.z, f[4], f[5]);
    CVT2(u.w, f[6], f[7]);
    return u;
}

// ---------------- prep kernel: 288 blocks x 256 threads ----------------
// blocks 0..255 : gallery rows (warp per row); 256..287 : queries (warp per q)
__global__ __launch_bounds__(256) void prep_kernel(
        const float* __restrict__ qf,
        const float* __restrict__ qi,
        const float* __restrict__ gal,
        const float* __restrict__ gamma,
        const float* __restrict__ beta,
        const float* __restrict__ mean,
        const float* __restrict__ var) {
    const int bx   = blockIdx.x;
    const int warp = threadIdx.x >> 5;
    const int lane = threadIdx.x & 31;

    if (bx < 256) {
        const int i = bx * 8 + warp;
        float x[8];
        {
            const float4* s4 = (const float4*)&gal[(size_t)i * DD + lane * 8];
            *(float4*)&x[0] = s4[0];
            *(float4*)&x[4] = s4[1];
        }
        float ss = 0.f;
        #pragma unroll
        for (int j = 0; j < 8; j++) ss += x[j] * x[j];
        ss = warpSum(ss);
        float inv = 1.f / fmaxf(sqrtf(ss), 1e-12f);
        float g[8];
        #pragma unroll
        for (int j = 0; j < 8; j++) g[j] = x[j] * inv;
        *(uint4*)&d_Gb[(size_t)i * DD + lane * 8] = pack8(g);
    } else {
        const int q = (bx - 256) * 8 + warp;

        float ga[8], be[8], me[8], va[8], x[8], y[8];
        {
            const float4* s;
            s = (const float4*)&gamma[lane * 8]; *(float4*)&ga[0] = s[0]; *(float4*)&ga[4] = s[1];
            s = (const float4*)&beta [lane * 8]; *(float4*)&be[0] = s[0]; *(float4*)&be[4] = s[1];
            s = (const float4*)&mean [lane * 8]; *(float4*)&me[0] = s[0]; *(float4*)&me[4] = s[1];
            s = (const float4*)&var  [lane * 8]; *(float4*)&va[0] = s[0]; *(float4*)&va[4] = s[1];
            s = (const float4*)&qf[(size_t)q * DD + lane * 8]; *(float4*)&x[0] = s[0]; *(float4*)&x[4] = s[1];
            s = (const float4*)&qi[(size_t)q * DD + lane * 8]; *(float4*)&y[0] = s[0]; *(float4*)&y[4] = s[1];
        }

        float istd[8], B[8];
        float xs = 0.f, ys = 0.f;
        #pragma unroll
        for (int j = 0; j < 8; j++) {
            istd[j] = ga[j] * rsqrtf(va[j] + 1e-5f);
            B[j] = be[j] - me[j] * istd[j];
            xs += x[j] * x[j];
            ys += y[j] * y[j];
        }
        xs = warpSum(xs);
        ys = warpSum(ys);
        float xin = 1.f / fmaxf(sqrtf(xs), 1e-12f);
        float yin = 1.f / fmaxf(sqrtf(ys), 1e-12f);

        float A[8], fq[8];
        float fs = 0.f;
        #pragma unroll
        for (int j = 0; j < 8; j++) {
            float xn = x[j] * xin;
            float gate = 1.f / (1.f + __expf(-xn * 5.0f));  // sigmoid(xn/0.2)
            A[j] = gate * istd[j];
            float yn = y[j] * yin;
            fq[j] = yn * A[j] + B[j];
            fs += fq[j] * fq[j];
        }
        fs = warpSum(fs);
        float fin = 1.f / fmaxf(sqrtf(fs), 1e-12f);

        float Cv[8], A2v[8], ABv[8];
        float c0 = 0.f;
        #pragma unroll
        for (int j = 0; j < 8; j++) {
            float fqn = fq[j] * fin;
            Cv[j]  = fqn * A[j];
            A2v[j] = A[j] * A[j];
            ABv[j] = 2.f * A[j] * B[j];
            c0 += fqn * B[j];
        }
        c0 = warpSum(c0);
        if (lane == 0) d_c0[q] = c0;

        *(uint4*)&d_Cb [(size_t)q * DD + lane * 8] = pack8(Cv);
        *(uint4*)&d_A2b[(size_t)q * DD + lane * 8] = pack8(A2v);
        *(uint4*)&d_ABb[(size_t)q * DD + lane * 8] = pack8(ABv);

        if (q == 0) {
            float b0 = 0.f;
            #pragma unroll
            for (int j = 0; j < 8; j++) b0 += B[j] * B[j];
            b0 = warpSum(b0);
            if (lane == 0) d_b0 = b0;
        }
    }
}

// ---------------- HMMA scoring kernel ----------------
// grid (II/TM, QD/TN) = (16, 8) = 128 CTAs; 512 threads = 16 warps (4 i x 4 q).
// Single-shot: cp.async the whole K=256 working set (118 KB), one wait + one
// syncthreads, then a straight barrier-free HMMA sweep. G2 fragments derived
// in registers by bf16x2 squaring of G fragments.
// s1 = C.G^T ; s2 = A2.G2^T + AB.G^T ; score = sigmoid((s1+c0)/sqrt(s2+b0)).
extern __shared__ __align__(16) char dyn_smem[];

__global__ __launch_bounds__(512) void score_kernel(float* __restrict__ out) {
    const int tid  = threadIdx.x;
    const int warp = tid >> 5;
    const int lane = tid & 31;
    const int wm = warp & 3;       // i block (32 rows)
    const int wn = warp >> 2;      // q block (8 cols)
    const int i0 = blockIdx.x * TM;
    const int q0 = blockIdx.y * TN;

    const uint32_t sb = (uint32_t)__cvta_generic_to_shared(dyn_smem);

    // ---- single-shot async load of the full working set ----
    // G: 128 rows x 32 16B-units = 4096 units -> 8 per thread
    #pragma unroll
    for (int j = 0; j < 8; j++) {
        int u = tid + 512 * j;
        int row = u >> 5;             // 0..127
        int c16 = u & 31;             // 16B unit in 512B row
        const size_t src = (size_t)(i0 + row) * DD + c16 * 8;
        CP16(sb + OFF_G + row * SKB + c16 * 16, &d_Gb[src]);
    }
    // coeffs: 3 arrays x 32 rows x 32 units = 1024 units each -> 2 per thread
    #pragma unroll
    for (int j = 0; j < 2; j++) {
        int u = tid + 512 * j;
        int row = u >> 5;             // 0..31
        int c16 = u & 31;
        const size_t src = (size_t)(q0 + row) * DD + c16 * 8;
        uint32_t dst = row * SKB + c16 * 16;
        CP16(sb + OFF_C  + dst, &d_Cb [src]);
        CP16(sb + OFF_A2 + dst, &d_A2b[src]);
        CP16(sb + OFF_AB + dst, &d_ABb[src]);
    }
    CPCOMMIT();
    CPWAIT0();
    __syncthreads();

    // ---- straight HMMA over K = 256, no barriers ----
    float s1[2][4], s2[2][4];
    #pragma unroll
    for (int ma = 0; ma < 2; ma++)
        #pragma unroll
        for (int r = 0; r < 4; r++) { s1[ma][r] = 0.f; s2[ma][r] = 0.f; }

    const int subA = lane >> 3;
    const int arow = (lane & 7) + (subA & 1) * 8;
    const int akof = (subA >> 1) * 16;
    const int brow = lane & 7;
    const int bkof = (lane >> 3) * 16;

    const uint32_t gA0 = sb + OFF_G  + (wm * 32 + arow) * SKB + akof;
    const uint32_t gA1 = gA0 + 16 * SKB;
    const uint32_t cB  = sb + OFF_C  + (wn * 8 + brow) * SKB + bkof;
    const uint32_t a2B = sb + OFF_A2 + (wn * 8 + brow) * SKB + bkof;
    const uint32_t abB = sb + OFF_AB + (wn * 8 + brow) * SKB + bkof;

    #pragma unroll
    for (int p = 0; p < 8; p++) {              // 8 pairs of k16 (k32 each)
        const uint32_t pb = p * 64;            // 32 bf16 = 64 B

        uint32_t bC[4], bA2[4], bAB[4];
        LDSM_X4(bC[0],  bC[1],  bC[2],  bC[3],  cB  + pb);
        LDSM_X4(bA2[0], bA2[1], bA2[2], bA2[3], a2B + pb);
        LDSM_X4(bAB[0], bAB[1], bAB[2], bAB[3], abB + pb);

        #pragma unroll
        for (int e = 0; e < 2; e++) {
            const uint32_t kb = pb + e * 32;
            uint32_t aG[2][4], aG2[2][4];
            LDSM_X4(aG[0][0], aG[0][1], aG[0][2], aG[0][3], gA0 + kb);
            LDSM_X4(aG[1][0], aG[1][1], aG[1][2], aG[1][3], gA1 + kb);
            #pragma unroll
            for (int ma = 0; ma < 2; ma++)
                #pragma unroll
                for (int r = 0; r < 4; r++)
                    SQR_BF16X2(aG2[ma][r], aG[ma][r]);

            #pragma unroll
            for (int ma = 0; ma < 2; ma++) {
                MMA16816(s1[ma], aG[ma],  bC[2*e],  bC[2*e+1]);
                MMA16816(s2[ma], aG2[ma], bA2[2*e], bA2[2*e+1]);
                MMA16816(s2[ma], aG[ma],  bAB[2*e], bAB[2*e+1]);
            }
        }
    }

    // ---- epilogue ----
    const float b0 = d_b0;
    const int rbase = lane >> 2;
    const int cbase = 2 * (lane & 3);
    const float c0a = d_c0[q0 + wn * 8 + cbase];
    const float c0b = d_c0[q0 + wn * 8 + cbase + 1];
    #pragma unroll
    for (int ma = 0; ma < 2; ma++) {
        #pragma unroll
        for (int r = 0; r < 4; r++) {
            int i = i0 + wm * 32 + ma * 16 + rbase + (r >> 1) * 8;
            int q = q0 + wn * 8 + cbase + (r & 1);
            float v1 = s1[ma][r] + ((r & 1) ? c0b : c0a);
            float v2 = s2[ma][r] + b0;
            float val = v1 * rsqrtf(fmaxf(v2, 1e-24f));
            out[(size_t)q * II + i] = 1.f / (1.f + __expf(-val));
        }
    }
}

extern "C" void kernel_launch(void* const* d_in, const int* in_sizes, int n_in,
                              void* d_out, int out_size) {
    const float* query_feats       = (const float*)d_in[0];
    const float* query_img_feats   = (const float*)d_in[1];
    const float* gallery_img_feats = (const float*)d_in[2];
    const float* bn_gamma          = (const float*)d_in[3];
    const float* bn_beta           = (const float*)d_in[4];
    const float* bn_mean           = (const float*)d_in[5];
    const float* bn_var            = (const float*)d_in[6];
    float* out = (float*)d_out;

    cudaFuncSetAttribute(score_kernel,
                         cudaFuncAttributeMaxDynamicSharedMemorySize, SMEM_SZ);

    prep_kernel<<<288, 256>>>(query_feats, query_img_feats, gallery_img_feats,
                              bn_gamma, bn_beta, bn_mean, bn_var);
    dim3 grid(II / TM, QD / TN);
    score_kernel<<<grid, 512, SMEM_SZ>>>(out);
}